// round 2
// baseline (speedup 1.0000x reference)
#include <cuda_runtime.h>

// Problem constants (fixed shapes for this dataset)
#define N_NODES 50000
#define N_BATCH 4
#define FEAT    32      // input feature dim, hidden1 dim, output dim
#define H2DIM   30      // hidden2 dim
#define ACC_W   32      // padded accumulator width (30 -> 32 for float4 alignment)

#define BN_MAX (N_BATCH * N_NODES)

// Device scratch (allowed: __device__ globals, no runtime allocation)
__device__ float g_Pa[BN_MAX * FEAT];     // x @ W1[0:32]
__device__ float g_Pb[BN_MAX * FEAT];     // x @ W1[32:64] + b1
__device__ float g_acc[BN_MAX * ACC_W];   // scatter accumulator (padded to 32)
__device__ float g_sum, g_sumsq;
__device__ float g_mean, g_invstd;
__device__ int   g_is32;                  // 1 if edge_index is int32, 0 if int64

__device__ __forceinline__ float sigf(float x) {
    return __fdividef(1.0f, 1.0f + __expf(-x));
}

// ---------------------------------------------------------------------------
// Zero accumulator + stats
// ---------------------------------------------------------------------------
__global__ void k_zero(int n_f4) {
    int i = blockIdx.x * blockDim.x + threadIdx.x;
    float4* p = reinterpret_cast<float4*>(g_acc);
    if (i < n_f4) p[i] = make_float4(0.f, 0.f, 0.f, 0.f);
    if (i == 0) { g_sum = 0.f; g_sumsq = 0.f; g_is32 = 0; }
}

// ---------------------------------------------------------------------------
// Detect edge_index dtype: if the data is int64 (values < 2^31, nonnegative),
// every odd 32-bit word of the first 2048 elements is 0. If int32, those odd
// words are random node indices (~all nonzero).
// ---------------------------------------------------------------------------
__global__ void k_detect(const int* __restrict__ idx) {
    int t = blockIdx.x * blockDim.x + threadIdx.x;
    if (t < 2048) {
        if (idx[2 * t + 1] != 0) g_is32 = 1;   // benign race: only writes 1
    }
}

// ---------------------------------------------------------------------------
// edge_attr mean / std (ddof=1)
// ---------------------------------------------------------------------------
__global__ void k_stats(const float* __restrict__ ea, int E) {
    float s = 0.f, ss = 0.f;
    for (int i = blockIdx.x * blockDim.x + threadIdx.x; i < E;
         i += gridDim.x * blockDim.x) {
        float v = ea[i];
        s += v; ss += v * v;
    }
#pragma unroll
    for (int o = 16; o > 0; o >>= 1) {
        s  += __shfl_down_sync(0xffffffffu, s, o);
        ss += __shfl_down_sync(0xffffffffu, ss, o);
    }
    __shared__ float shs[8], shss[8];
    int w = threadIdx.x >> 5, l = threadIdx.x & 31;
    if (l == 0) { shs[w] = s; shss[w] = ss; }
    __syncthreads();
    if (threadIdx.x == 0) {
        float a = 0.f, b = 0.f;
        int nw = blockDim.x >> 5;
        for (int j = 0; j < nw; j++) { a += shs[j]; b += shss[j]; }
        atomicAdd(&g_sum, a);
        atomicAdd(&g_sumsq, b);
    }
}

__global__ void k_finalize(int E) {
    float s = g_sum, ss = g_sumsq;
    float mean = s / (float)E;
    float var  = (ss - s * s / (float)E) / (float)(E - 1);
    g_mean   = mean;
    g_invstd = rsqrtf(var);
}

// ---------------------------------------------------------------------------
// Per-(batch,node) projections: Pa = x@W1[0:32], Pb = x@W1[32:64] + b1.
// One warp per row; lane = output column; x row broadcast via shfl.
// ---------------------------------------------------------------------------
__global__ void __launch_bounds__(256) k_proj(const float* __restrict__ x,
                                              const float* __restrict__ W1,
                                              const float* __restrict__ b1,
                                              int BN) {
    __shared__ float W1s[64 * 32];
    __shared__ float b1s[32];
    for (int i = threadIdx.x; i < 64 * 32; i += blockDim.x) W1s[i] = W1[i];
    if (threadIdx.x < 32) b1s[threadIdx.x] = b1[threadIdx.x];
    __syncthreads();

    int warp = (blockIdx.x * blockDim.x + threadIdx.x) >> 5;
    int lane = threadIdx.x & 31;
    if (warp >= BN) return;

    float xv = x[warp * 32 + lane];
    float pa = 0.f;
    float pb = b1s[lane];
#pragma unroll
    for (int k = 0; k < 32; k++) {
        float xk = __shfl_sync(0xffffffffu, xv, k);
        pa = fmaf(xk, W1s[k * 32 + lane], pa);
        pb = fmaf(xk, W1s[(32 + k) * 32 + lane], pb);
    }
    g_Pa[warp * 32 + lane] = pa;
    g_Pb[warp * 32 + lane] = pb;
}

// ---------------------------------------------------------------------------
// Edge kernel: one thread per edge, SEQUENTIAL loop over batches
// (#pragma unroll 1 is load-bearing: full unroll made ptxas keep 4 batches
// of h1/h2 live -> ~4KB/thread local spill -> 1.3GB driver lmem alloc).
// h1 = sigmoid(Pa[src] + Pb[tgt] + ea_n * W1c); h2 = sigmoid(h1@W2 + b2).
// acc[tgt] += h2; acc[src] -= h2 via float4 atomics (padded cols are zero).
// ---------------------------------------------------------------------------
__global__ void __launch_bounds__(256) k_edge(const int* __restrict__ idx,
                                              const float* __restrict__ ea,
                                              const float* __restrict__ W1,
                                              const float* __restrict__ W2,
                                              const float* __restrict__ b2,
                                              int E) {
    __shared__ float W2s[32 * 30];
    __shared__ float b2s[30];
    __shared__ float W1cs[32];
    __shared__ float s_mean, s_invstd;
    __shared__ int   s_is32;

    for (int i = threadIdx.x; i < 32 * 30; i += blockDim.x) W2s[i] = W2[i];
    if (threadIdx.x < 30) b2s[threadIdx.x] = b2[threadIdx.x];
    if (threadIdx.x < 32) W1cs[threadIdx.x] = W1[64 * 32 + threadIdx.x];
    if (threadIdx.x == 0) { s_mean = g_mean; s_invstd = g_invstd; s_is32 = g_is32; }
    __syncthreads();

    int e = blockIdx.x * blockDim.x + threadIdx.x;
    if (e >= E) return;

    int src, tgt;
    if (s_is32) {
        src = idx[e];
        tgt = idx[E + e];
    } else {
        src = idx[2 * e];
        tgt = idx[2 * E + 2 * e];
    }
    float eav = (ea[e] - s_mean) * s_invstd;

    const float4* pa0 = reinterpret_cast<const float4*>(g_Pa + src * 32);
    const float4* pb0 = reinterpret_cast<const float4*>(g_Pb + tgt * 32);
    float4* at0 = reinterpret_cast<float4*>(g_acc + tgt * ACC_W);
    float4* as0 = reinterpret_cast<float4*>(g_acc + src * ACC_W);
    const int rowstride_f4 = N_NODES * 32 / 4;   // per-batch stride in float4

#pragma unroll 1
    for (int b = 0; b < N_BATCH; b++) {
        const float4* pa = pa0 + b * rowstride_f4;
        const float4* pb = pb0 + b * rowstride_f4;

        float h1[32];
#pragma unroll
        for (int q = 0; q < 8; q++) {
            float4 a = pa[q];
            float4 c = pb[q];
            h1[q * 4 + 0] = sigf(a.x + c.x + eav * W1cs[q * 4 + 0]);
            h1[q * 4 + 1] = sigf(a.y + c.y + eav * W1cs[q * 4 + 1]);
            h1[q * 4 + 2] = sigf(a.z + c.z + eav * W1cs[q * 4 + 2]);
            h1[q * 4 + 3] = sigf(a.w + c.w + eav * W1cs[q * 4 + 3]);
        }

        float h2[32];
#pragma unroll
        for (int j = 0; j < 30; j += 2) {
            float s0 = b2s[j];
            float s1 = b2s[j + 1];
#pragma unroll
            for (int k = 0; k < 32; k++) {
                float hk = h1[k];
                s0 = fmaf(hk, W2s[k * 30 + j], s0);
                s1 = fmaf(hk, W2s[k * 30 + j + 1], s1);
            }
            h2[j]     = sigf(s0);
            h2[j + 1] = sigf(s1);
        }
        h2[30] = 0.f;
        h2[31] = 0.f;

        float4* at = at0 + b * rowstride_f4;
        float4* as = as0 + b * rowstride_f4;
#pragma unroll
        for (int q = 0; q < 8; q++) {
            atomicAdd(at + q, make_float4( h2[q*4+0],  h2[q*4+1],  h2[q*4+2],  h2[q*4+3]));
            atomicAdd(as + q, make_float4(-h2[q*4+0], -h2[q*4+1], -h2[q*4+2], -h2[q*4+3]));
        }
    }
}

// ---------------------------------------------------------------------------
// Output: out = sigmoid(acc[:, :30] @ W3 + b3). One warp per row.
// ---------------------------------------------------------------------------
__global__ void __launch_bounds__(256) k_out(const float* __restrict__ W3,
                                             const float* __restrict__ b3,
                                             float* __restrict__ out,
                                             int BN) {
    __shared__ float W3s[30 * 32];
    __shared__ float b3s[32];
    for (int i = threadIdx.x; i < 30 * 32; i += blockDim.x) W3s[i] = W3[i];
    if (threadIdx.x < 32) b3s[threadIdx.x] = b3[threadIdx.x];
    __syncthreads();

    int warp = (blockIdx.x * blockDim.x + threadIdx.x) >> 5;
    int lane = threadIdx.x & 31;
    if (warp >= BN) return;

    float av = g_acc[warp * ACC_W + lane];   // lanes 30/31 read padding (unused)
    float o = b3s[lane];
#pragma unroll
    for (int k = 0; k < 30; k++) {
        float ak = __shfl_sync(0xffffffffu, av, k);
        o = fmaf(ak, W3s[k * 32 + lane], o);
    }
    out[warp * 32 + lane] = sigf(o);
}

// ---------------------------------------------------------------------------
extern "C" void kernel_launch(void* const* d_in, const int* in_sizes, int n_in,
                              void* d_out, int out_size) {
    const float* x  = (const float*)d_in[0];
    const int*   ix = (const int*)  d_in[1];
    const float* ea = (const float*)d_in[2];
    const float* W1 = (const float*)d_in[3];
    const float* b1 = (const float*)d_in[4];
    const float* W2 = (const float*)d_in[5];
    const float* b2 = (const float*)d_in[6];
    const float* W3 = (const float*)d_in[7];
    const float* b3 = (const float*)d_in[8];

    int E  = in_sizes[2];            // edge_attr has E elements
    int BN = in_sizes[0] / FEAT;     // B * N rows

    int n_f4 = BN * ACC_W / 4;
    k_zero<<<(n_f4 + 255) / 256, 256>>>(n_f4);
    k_detect<<<8, 256>>>(ix);
    k_stats<<<256, 256>>>(ea, E);
    k_finalize<<<1, 1>>>(E);
    k_proj<<<(BN + 7) / 8, 256>>>(x, W1, b1, BN);
    k_edge<<<(E + 255) / 256, 256>>>(ix, ea, W1, W2, b2, E);
    k_out<<<(BN + 7) / 8, 256>>>(W3, b3, (float*)d_out, BN);
}

// round 3
// speedup vs baseline: 6.0839x; 6.0839x over previous
#include <cuda_runtime.h>

// Problem constants (fixed shapes for this dataset)
#define N_NODES 50000
#define N_BATCH 4
#define FEAT    32      // input feature dim, hidden1 dim, output dim
#define H2DIM   30      // hidden2 dim
#define ACC_W   32      // padded accumulator width (30 -> 32)

#define BN_MAX (N_BATCH * N_NODES)

// Device scratch (allowed: __device__ globals, no runtime allocation)
__device__ float g_Pa[BN_MAX * FEAT];     // x @ W1[0:32]
__device__ float g_Pb[BN_MAX * FEAT];     // x @ W1[32:64] + b1
__device__ float g_acc[BN_MAX * ACC_W];   // scatter accumulator (padded to 32)
__device__ float g_sum, g_sumsq;
__device__ float g_mean, g_invstd;
__device__ int   g_is32;                  // 1 if edge_index is int32, 0 if int64

__device__ __forceinline__ float sigf(float x) {
    return __fdividef(1.0f, 1.0f + __expf(-x));
}

// ---------------------------------------------------------------------------
// Zero accumulator + stats
// ---------------------------------------------------------------------------
__global__ void k_zero(int n_f4) {
    int i = blockIdx.x * blockDim.x + threadIdx.x;
    float4* p = reinterpret_cast<float4*>(g_acc);
    if (i < n_f4) p[i] = make_float4(0.f, 0.f, 0.f, 0.f);
    if (i == 0) { g_sum = 0.f; g_sumsq = 0.f; g_is32 = 0; }
}

// ---------------------------------------------------------------------------
// Detect edge_index dtype: if int64 (values < 2^31, nonnegative), every odd
// 32-bit word of the first 2048 elements is 0.
// ---------------------------------------------------------------------------
__global__ void k_detect(const int* __restrict__ idx) {
    int t = blockIdx.x * blockDim.x + threadIdx.x;
    if (t < 2048) {
        if (idx[2 * t + 1] != 0) g_is32 = 1;   // benign race: only writes 1
    }
}

// ---------------------------------------------------------------------------
// edge_attr mean / std (ddof=1)
// ---------------------------------------------------------------------------
__global__ void k_stats(const float* __restrict__ ea, int E) {
    float s = 0.f, ss = 0.f;
    for (int i = blockIdx.x * blockDim.x + threadIdx.x; i < E;
         i += gridDim.x * blockDim.x) {
        float v = ea[i];
        s += v; ss += v * v;
    }
#pragma unroll
    for (int o = 16; o > 0; o >>= 1) {
        s  += __shfl_down_sync(0xffffffffu, s, o);
        ss += __shfl_down_sync(0xffffffffu, ss, o);
    }
    __shared__ float shs[8], shss[8];
    int w = threadIdx.x >> 5, l = threadIdx.x & 31;
    if (l == 0) { shs[w] = s; shss[w] = ss; }
    __syncthreads();
    if (threadIdx.x == 0) {
        float a = 0.f, b = 0.f;
        int nw = blockDim.x >> 5;
        for (int j = 0; j < nw; j++) { a += shs[j]; b += shss[j]; }
        atomicAdd(&g_sum, a);
        atomicAdd(&g_sumsq, b);
    }
}

__global__ void k_finalize(int E) {
    float s = g_sum, ss = g_sumsq;
    float mean = s / (float)E;
    float var  = (ss - s * s / (float)E) / (float)(E - 1);
    g_mean   = mean;
    g_invstd = rsqrtf(var);
}

// ---------------------------------------------------------------------------
// Per-(batch,node) projections: Pa = x@W1[0:32], Pb = x@W1[32:64] + b1.
// One warp per row; lane = output column; x row broadcast via shfl.
// ---------------------------------------------------------------------------
__global__ void __launch_bounds__(256) k_proj(const float* __restrict__ x,
                                              const float* __restrict__ W1,
                                              const float* __restrict__ b1,
                                              int BN) {
    __shared__ float W1s[64 * 32];
    __shared__ float b1s[32];
    for (int i = threadIdx.x; i < 64 * 32; i += blockDim.x) W1s[i] = W1[i];
    if (threadIdx.x < 32) b1s[threadIdx.x] = b1[threadIdx.x];
    __syncthreads();

    int warp = (blockIdx.x * blockDim.x + threadIdx.x) >> 5;
    int lane = threadIdx.x & 31;
    if (warp >= BN) return;

    float xv = x[warp * 32 + lane];
    float pa = 0.f;
    float pb = b1s[lane];
#pragma unroll
    for (int k = 0; k < 32; k++) {
        float xk = __shfl_sync(0xffffffffu, xv, k);
        pa = fmaf(xk, W1s[k * 32 + lane], pa);
        pb = fmaf(xk, W1s[(32 + k) * 32 + lane], pb);
    }
    g_Pa[warp * 32 + lane] = pa;
    g_Pb[warp * 32 + lane] = pb;
}

// ---------------------------------------------------------------------------
// Edge kernel, warp-per-edge layout (lane = feature / output column).
//   - coalesced gathers: warp reads Pa[src] / Pb[tgt] rows (1 line each)
//   - h1_lane computed per lane; layer-2 delivers h1 via warp shuffles
//   - W2 column j (j = lane) held in 32 registers per lane
//   - coalesced scatter: RED.32 per lane into one 128B row
// All 4 batches unrolled (tiny per-batch state, no spill risk).
// ---------------------------------------------------------------------------
__global__ void __launch_bounds__(256) k_edge(const int* __restrict__ idx,
                                              const float* __restrict__ ea,
                                              const float* __restrict__ W1,
                                              const float* __restrict__ W2,
                                              const float* __restrict__ b2,
                                              int E) {
    const int lane = threadIdx.x & 31;
    const unsigned full = 0xffffffffu;

    // Per-lane constants
    float w1cv = W1[64 * 32 + lane];                       // edge-attr column
    float b2v  = (lane < H2DIM) ? b2[lane] : 0.f;
    float w2c[32];
#pragma unroll
    for (int k = 0; k < 32; k++)
        w2c[k] = (lane < H2DIM) ? W2[k * H2DIM + lane] : 0.f;

    float mean   = g_mean;
    float invstd = g_invstd;
    int   is32   = g_is32;

    int warp_global = (blockIdx.x * blockDim.x + threadIdx.x) >> 5;
    int base = warp_global * 32;
    if (base >= E) return;

    // Each lane loads one edge's metadata (coalesced), then shuffle-iterate.
    int e = base + lane;
    int src = 0, tgt = 0;
    float eav = 0.f;
    if (e < E) {
        if (is32) {
            src = idx[e];
            tgt = idx[E + e];
        } else {
            src = idx[2 * e];
            tgt = idx[2 * E + 2 * e];
        }
        eav = (ea[e] - mean) * invstd;
    }
    int cnt = min(32, E - base);

    const int BSTRIDE = N_NODES * 32;   // per-batch stride in floats

#pragma unroll 1
    for (int i = 0; i < cnt; i++) {
        int   s_i = __shfl_sync(full, src, i);
        int   t_i = __shfl_sync(full, tgt, i);
        float ev  = __shfl_sync(full, eav, i);

        const float* paB = g_Pa + s_i * 32 + lane;
        const float* pbB = g_Pb + t_i * 32 + lane;

        // h1 per batch (lane = hidden1 feature)
        float h1v[N_BATCH];
#pragma unroll
        for (int b = 0; b < N_BATCH; b++) {
            float pa = paB[b * BSTRIDE];
            float pb = pbB[b * BSTRIDE];
            h1v[b] = sigf(pa + pb + ev * w1cv);
        }

        // layer 2: lane j accumulates over k via shuffle broadcast
        float sv[N_BATCH];
#pragma unroll
        for (int b = 0; b < N_BATCH; b++) sv[b] = b2v;
#pragma unroll
        for (int k = 0; k < 32; k++) {
            float w = w2c[k];
#pragma unroll
            for (int b = 0; b < N_BATCH; b++) {
                float hk = __shfl_sync(full, h1v[b], k);
                sv[b] = fmaf(hk, w, sv[b]);
            }
        }

        // sigmoid + coalesced scatter (lanes >= 30 inactive)
#pragma unroll
        for (int b = 0; b < N_BATCH; b++) {
            if (lane < H2DIM) {
                float h2 = sigf(sv[b]);
                atomicAdd(&g_acc[(t_i + b * N_NODES) * ACC_W + lane],  h2);
                atomicAdd(&g_acc[(s_i + b * N_NODES) * ACC_W + lane], -h2);
            }
        }
    }
}

// ---------------------------------------------------------------------------
// Output: out = sigmoid(acc[:, :30] @ W3 + b3). One warp per row.
// ---------------------------------------------------------------------------
__global__ void __launch_bounds__(256) k_out(const float* __restrict__ W3,
                                             const float* __restrict__ b3,
                                             float* __restrict__ out,
                                             int BN) {
    __shared__ float W3s[30 * 32];
    __shared__ float b3s[32];
    for (int i = threadIdx.x; i < 30 * 32; i += blockDim.x) W3s[i] = W3[i];
    if (threadIdx.x < 32) b3s[threadIdx.x] = b3[threadIdx.x];
    __syncthreads();

    int warp = (blockIdx.x * blockDim.x + threadIdx.x) >> 5;
    int lane = threadIdx.x & 31;
    if (warp >= BN) return;

    float av = g_acc[warp * ACC_W + lane];   // lanes 30/31 read padding (unused)
    float o = b3s[lane];
#pragma unroll
    for (int k = 0; k < 30; k++) {
        float ak = __shfl_sync(0xffffffffu, av, k);
        o = fmaf(ak, W3s[k * 32 + lane], o);
    }
    out[warp * 32 + lane] = sigf(o);
}

// ---------------------------------------------------------------------------
extern "C" void kernel_launch(void* const* d_in, const int* in_sizes, int n_in,
                              void* d_out, int out_size) {
    const float* x  = (const float*)d_in[0];
    const int*   ix = (const int*)  d_in[1];
    const float* ea = (const float*)d_in[2];
    const float* W1 = (const float*)d_in[3];
    const float* b1 = (const float*)d_in[4];
    const float* W2 = (const float*)d_in[5];
    const float* b2 = (const float*)d_in[6];
    const float* W3 = (const float*)d_in[7];
    const float* b3 = (const float*)d_in[8];

    int E  = in_sizes[2];            // edge_attr has E elements
    int BN = in_sizes[0] / FEAT;     // B * N rows

    int n_f4 = BN * ACC_W / 4;
    k_zero<<<(n_f4 + 255) / 256, 256>>>(n_f4);
    k_detect<<<8, 256>>>(ix);
    k_stats<<<256, 256>>>(ea, E);
    k_finalize<<<1, 1>>>(E);
    k_proj<<<(BN + 7) / 8, 256>>>(x, W1, b1, BN);

    int warps = (E + 31) / 32;
    int blocks = (warps + 7) / 8;    // 8 warps (256 threads) per block
    k_edge<<<blocks, 256>>>(ix, ea, W1, W2, b2, E);

    k_out<<<(BN + 7) / 8, 256>>>(W3, b3, (float*)d_out, BN);
}

// round 4
// speedup vs baseline: 9.0545x; 1.4883x over previous
#include <cuda_runtime.h>
#include <cstdint>

// Problem constants (fixed shapes for this dataset)
#define N_NODES 50000
#define N_BATCH 4
#define FEAT    32      // input feature dim, hidden1 dim, output dim
#define H2DIM   30      // hidden2 dim
#define ACC_W   32      // padded accumulator width (30 -> 32)

#define BN_MAX (N_BATCH * N_NODES)

// Device scratch (allowed: __device__ globals, no runtime allocation)
__device__ float g_Pa[BN_MAX * FEAT];     // x @ W1[0:32]
__device__ float g_Pb[BN_MAX * FEAT];     // x @ W1[32:64] + b1
__device__ float g_acc[BN_MAX * ACC_W];   // scatter accumulator (padded to 32)
__device__ float g_sum, g_sumsq;
__device__ int   g_is32;                  // 1 if edge_index is int32, 0 if int64

// sigmoid via single MUFU.TANH: sig(x) = 0.5*tanh(x/2) + 0.5
__device__ __forceinline__ float sigf(float x) {
    float t;
    asm("tanh.approx.f32 %0, %1;" : "=f"(t) : "f"(x * 0.5f));
    return fmaf(t, 0.5f, 0.5f);
}

// ---------------------------------------------------------------------------
// Zero accumulator + stats init + dtype detect (folded)
// ---------------------------------------------------------------------------
__global__ void k_zero(int n_f4, const int* __restrict__ idx) {
    int i = blockIdx.x * blockDim.x + threadIdx.x;
    float4* p = reinterpret_cast<float4*>(g_acc);
    if (i < n_f4) p[i] = make_float4(0.f, 0.f, 0.f, 0.f);
    if (i == 0) { g_sum = 0.f; g_sumsq = 0.f; g_is32 = 0; }
    // dtype detect: if int64 (nonneg, < 2^31) every odd 32-bit word is 0
    if (i < 2048) {
        if (idx[2 * i + 1] != 0) g_is32 = 1;   // benign race: only writes 1
    }
}

// ---------------------------------------------------------------------------
// edge_attr sum / sumsq (mean/std finalized inside k_edge)
// ---------------------------------------------------------------------------
__global__ void k_stats(const float* __restrict__ ea, int E) {
    float s = 0.f, ss = 0.f;
    for (int i = blockIdx.x * blockDim.x + threadIdx.x; i < E;
         i += gridDim.x * blockDim.x) {
        float v = ea[i];
        s += v; ss += v * v;
    }
#pragma unroll
    for (int o = 16; o > 0; o >>= 1) {
        s  += __shfl_down_sync(0xffffffffu, s, o);
        ss += __shfl_down_sync(0xffffffffu, ss, o);
    }
    __shared__ float shs[8], shss[8];
    int w = threadIdx.x >> 5, l = threadIdx.x & 31;
    if (l == 0) { shs[w] = s; shss[w] = ss; }
    __syncthreads();
    if (threadIdx.x == 0) {
        float a = 0.f, b = 0.f;
        int nw = blockDim.x >> 5;
        for (int j = 0; j < nw; j++) { a += shs[j]; b += shss[j]; }
        atomicAdd(&g_sum, a);
        atomicAdd(&g_sumsq, b);
    }
}

// ---------------------------------------------------------------------------
// Per-(batch,node) projections: Pa = x@W1[0:32], Pb = x@W1[32:64] + b1.
// One warp per row; lane = output column; x row broadcast via shfl.
// ---------------------------------------------------------------------------
__global__ void __launch_bounds__(256) k_proj(const float* __restrict__ x,
                                              const float* __restrict__ W1,
                                              const float* __restrict__ b1,
                                              int BN) {
    __shared__ float W1s[64 * 32];
    __shared__ float b1s[32];
    for (int i = threadIdx.x; i < 64 * 32; i += blockDim.x) W1s[i] = W1[i];
    if (threadIdx.x < 32) b1s[threadIdx.x] = b1[threadIdx.x];
    __syncthreads();

    int warp = (blockIdx.x * blockDim.x + threadIdx.x) >> 5;
    int lane = threadIdx.x & 31;
    if (warp >= BN) return;

    float xv = x[warp * 32 + lane];
    float pa = 0.f;
    float pb = b1s[lane];
#pragma unroll
    for (int k = 0; k < 32; k++) {
        float xk = __shfl_sync(0xffffffffu, xv, k);
        pa = fmaf(xk, W1s[k * 32 + lane], pa);
        pb = fmaf(xk, W1s[(32 + k) * 32 + lane], pb);
    }
    g_Pa[warp * 32 + lane] = pa;
    g_Pb[warp * 32 + lane] = pb;
}

// ---------------------------------------------------------------------------
// Edge kernel, warp-per-edge layout (lane = feature / output column).
//   - coalesced gathers: warp reads Pa[src] / Pb[tgt] rows (1 line each)
//   - h1 (per-lane, 4 batches) stored as one float4 STS -> broadcast LDS.128
//     in the layer-2 k-loop (replaces 128 SHFLs with 32 LDS)
//   - batch accumulators packed: 2x fma.rn.f32x2 per k
//   - coalesced scatter: RED.32 per lane into one 128B row
// ---------------------------------------------------------------------------
__global__ void __launch_bounds__(256) k_edge(const int* __restrict__ idx,
                                              const float* __restrict__ ea,
                                              const float* __restrict__ W1,
                                              const float* __restrict__ W2,
                                              const float* __restrict__ b2,
                                              int E) {
    const int lane = threadIdx.x & 31;
    const int wid  = threadIdx.x >> 5;
    const unsigned full = 0xffffffffu;

    // double-buffered per-warp h1 tile: [warp][buf][k][batch]
    __shared__ __align__(16) float h1s[8][2][32][4];

    // Per-lane constants
    const bool act = (lane < H2DIM);
    float w1cv = W1[64 * 32 + lane];                 // edge-attr column of W1
    float b2v  = act ? b2[lane] : 0.f;
    float w2c[32];
#pragma unroll
    for (int k = 0; k < 32; k++)
        w2c[k] = act ? W2[k * H2DIM + lane] : 0.f;

    // finalize stats locally (cheap, uniform)
    float s  = g_sum, ss = g_sumsq;
    float mean   = s / (float)E;
    float invstd = rsqrtf((ss - s * s / (float)E) / (float)(E - 1));
    int   is32   = g_is32;

    int warp_global = (blockIdx.x * blockDim.x + threadIdx.x) >> 5;
    int base = warp_global * 32;
    if (base >= E) return;

    // Each lane loads one edge's metadata (coalesced), then shuffle-iterate.
    int e = base + lane;
    int src = 0, tgt = 0;
    float eav = 0.f;
    if (e < E) {
        if (is32) {
            src = idx[e];
            tgt = idx[E + e];
        } else {
            src = idx[2 * e];
            tgt = idx[2 * E + 2 * e];
        }
        eav = (ea[e] - mean) * invstd;
    }
    int cnt = min(32, E - base);

    const int BSTRIDE = N_NODES * 32;   // per-batch stride in floats

#pragma unroll 1
    for (int i = 0; i < cnt; i++) {
        int   s_i = __shfl_sync(full, src, i);
        int   t_i = __shfl_sync(full, tgt, i);
        float ev  = __shfl_sync(full, eav, i);
        int   buf = i & 1;

        const float* paB = g_Pa + s_i * 32 + lane;
        const float* pbB = g_Pb + t_i * 32 + lane;

        // h1 per batch (lane = hidden1 feature k)
        float4 h1v;
        h1v.x = sigf(paB[0 * BSTRIDE] + pbB[0 * BSTRIDE] + ev * w1cv);
        h1v.y = sigf(paB[1 * BSTRIDE] + pbB[1 * BSTRIDE] + ev * w1cv);
        h1v.z = sigf(paB[2 * BSTRIDE] + pbB[2 * BSTRIDE] + ev * w1cv);
        h1v.w = sigf(paB[3 * BSTRIDE] + pbB[3 * BSTRIDE] + ev * w1cv);

        *reinterpret_cast<float4*>(&h1s[wid][buf][lane][0]) = h1v;
        __syncwarp(full);

        // layer 2: lane j accumulates over k; h1 via broadcast LDS.128,
        // batch pairs packed into f32x2 FFMAs
        uint64_t s01, s23;
        asm("mov.b64 %0, {%1, %2};" : "=l"(s01) : "f"(b2v), "f"(b2v));
        s23 = s01;

        uint32_t saddr = (uint32_t)__cvta_generic_to_shared(&h1s[wid][buf][0][0]);
#pragma unroll
        for (int k = 0; k < 32; k++) {
            uint64_t h01, h23, wp;
            asm("ld.shared.v2.u64 {%0, %1}, [%2];"
                : "=l"(h01), "=l"(h23) : "r"(saddr + k * 16));
            asm("mov.b64 %0, {%1, %1};" : "=l"(wp) : "f"(w2c[k]));
            asm("fma.rn.f32x2 %0, %1, %2, %0;" : "+l"(s01) : "l"(h01), "l"(wp));
            asm("fma.rn.f32x2 %0, %1, %2, %0;" : "+l"(s23) : "l"(h23), "l"(wp));
        }

        float v0, v1, v2, v3;
        asm("mov.b64 {%0, %1}, %2;" : "=f"(v0), "=f"(v1) : "l"(s01));
        asm("mov.b64 {%0, %1}, %2;" : "=f"(v2), "=f"(v3) : "l"(s23));

        if (act) {
            float h2a = sigf(v0), h2b = sigf(v1), h2c = sigf(v2), h2d = sigf(v3);
            float* accT = g_acc + t_i * ACC_W + lane;
            float* accS = g_acc + s_i * ACC_W + lane;
            const int AB = N_NODES * ACC_W;
            atomicAdd(accT + 0 * AB,  h2a);
            atomicAdd(accS + 0 * AB, -h2a);
            atomicAdd(accT + 1 * AB,  h2b);
            atomicAdd(accS + 1 * AB, -h2b);
            atomicAdd(accT + 2 * AB,  h2c);
            atomicAdd(accS + 2 * AB, -h2c);
            atomicAdd(accT + 3 * AB,  h2d);
            atomicAdd(accS + 3 * AB, -h2d);
        }
    }
}

// ---------------------------------------------------------------------------
// Output: out = sigmoid(acc[:, :30] @ W3 + b3). One warp per row.
// ---------------------------------------------------------------------------
__global__ void __launch_bounds__(256) k_out(const float* __restrict__ W3,
                                             const float* __restrict__ b3,
                                             float* __restrict__ out,
                                             int BN) {
    __shared__ float W3s[30 * 32];
    __shared__ float b3s[32];
    for (int i = threadIdx.x; i < 30 * 32; i += blockDim.x) W3s[i] = W3[i];
    if (threadIdx.x < 32) b3s[threadIdx.x] = b3[threadIdx.x];
    __syncthreads();

    int warp = (blockIdx.x * blockDim.x + threadIdx.x) >> 5;
    int lane = threadIdx.x & 31;
    if (warp >= BN) return;

    float av = g_acc[warp * ACC_W + lane];   // lanes 30/31 read padding (unused)
    float o = b3s[lane];
#pragma unroll
    for (int k = 0; k < 30; k++) {
        float ak = __shfl_sync(0xffffffffu, av, k);
        o = fmaf(ak, W3s[k * 32 + lane], o);
    }
    out[warp * 32 + lane] = sigf(o);
}

// ---------------------------------------------------------------------------
extern "C" void kernel_launch(void* const* d_in, const int* in_sizes, int n_in,
                              void* d_out, int out_size) {
    const float* x  = (const float*)d_in[0];
    const int*   ix = (const int*)  d_in[1];
    const float* ea = (const float*)d_in[2];
    const float* W1 = (const float*)d_in[3];
    const float* b1 = (const float*)d_in[4];
    const float* W2 = (const float*)d_in[5];
    const float* b2 = (const float*)d_in[6];
    const float* W3 = (const float*)d_in[7];
    const float* b3 = (const float*)d_in[8];

    int E  = in_sizes[2];            // edge_attr has E elements
    int BN = in_sizes[0] / FEAT;     // B * N rows

    int n_f4 = BN * ACC_W / 4;
    k_zero<<<(n_f4 + 255) / 256, 256>>>(n_f4, ix);
    k_stats<<<256, 256>>>(ea, E);
    k_proj<<<(BN + 7) / 8, 256>>>(x, W1, b1, BN);

    int warps = (E + 31) / 32;
    int blocks = (warps + 7) / 8;    // 8 warps (256 threads) per block
    k_edge<<<blocks, 256>>>(ix, ea, W1, W2, b2, E);

    k_out<<<(BN + 7) / 8, 256>>>(W3, b3, (float*)d_out, BN);
}

// round 5
// speedup vs baseline: 10.1212x; 1.1178x over previous
#include <cuda_runtime.h>
#include <cstdint>

// Problem constants (fixed shapes for this dataset)
#define N_NODES 50000
#define N_BATCH 4
#define FEAT    32      // input feature dim, hidden1 dim, output dim
#define H2DIM   30      // hidden2 dim
#define ACC_W   32      // padded accumulator j-width (30 -> 32)

#define BN_MAX (N_BATCH * N_NODES)

// Device scratch. Layouts chosen for the edge kernel:
//   g_Pa4/g_Pb4 : [node][k]   -> float4 of the 4 batch values
//   g_acc       : [node][j][b] (j padded to 32), float4-alignable per (node,j)
__device__ float4 g_Pa4[N_NODES * FEAT];
__device__ float4 g_Pb4[N_NODES * FEAT];
__device__ float  g_acc[N_NODES * ACC_W * N_BATCH];
__device__ float  g_sum, g_sumsq;
__device__ int    g_is32;               // 1 if edge_index is int32, 0 if int64

// sigmoid via single MUFU.TANH: sig(x) = 0.5*tanh(x/2) + 0.5
__device__ __forceinline__ float sigf(float x) {
    float t;
    asm("tanh.approx.f32 %0, %1;" : "=f"(t) : "f"(x * 0.5f));
    return fmaf(t, 0.5f, 0.5f);
}

// ---------------------------------------------------------------------------
// Zero accumulator + stats init + dtype detect
// ---------------------------------------------------------------------------
__global__ void k_zero(int n_f4, const int* __restrict__ idx) {
    int i = blockIdx.x * blockDim.x + threadIdx.x;
    float4* p = reinterpret_cast<float4*>(g_acc);
    if (i < n_f4) p[i] = make_float4(0.f, 0.f, 0.f, 0.f);
    if (i == 0) { g_sum = 0.f; g_sumsq = 0.f; g_is32 = 0; }
    if (i < 2048) {
        if (idx[2 * i + 1] != 0) g_is32 = 1;   // benign race: only writes 1
    }
}

// ---------------------------------------------------------------------------
// edge_attr sum / sumsq (mean/std finalized inside k_edge)
// ---------------------------------------------------------------------------
__global__ void k_stats(const float* __restrict__ ea, int E) {
    float s = 0.f, ss = 0.f;
    for (int i = blockIdx.x * blockDim.x + threadIdx.x; i < E;
         i += gridDim.x * blockDim.x) {
        float v = ea[i];
        s += v; ss += v * v;
    }
#pragma unroll
    for (int o = 16; o > 0; o >>= 1) {
        s  += __shfl_down_sync(0xffffffffu, s, o);
        ss += __shfl_down_sync(0xffffffffu, ss, o);
    }
    __shared__ float shs[8], shss[8];
    int w = threadIdx.x >> 5, l = threadIdx.x & 31;
    if (l == 0) { shs[w] = s; shss[w] = ss; }
    __syncthreads();
    if (threadIdx.x == 0) {
        float a = 0.f, b = 0.f;
        int nw = blockDim.x >> 5;
        for (int j = 0; j < nw; j++) { a += shs[j]; b += shss[j]; }
        atomicAdd(&g_sum, a);
        atomicAdd(&g_sumsq, b);
    }
}

// ---------------------------------------------------------------------------
// Per-(batch,node) projections: Pa = x@W1[0:32], Pb = x@W1[32:64] + b1.
// One warp per (b,node) row; writes batch-interleaved float4 layout.
// ---------------------------------------------------------------------------
__global__ void __launch_bounds__(256) k_proj(const float* __restrict__ x,
                                              const float* __restrict__ W1,
                                              const float* __restrict__ b1,
                                              int BN) {
    __shared__ float W1s[64 * 32];
    __shared__ float b1s[32];
    for (int i = threadIdx.x; i < 64 * 32; i += blockDim.x) W1s[i] = W1[i];
    if (threadIdx.x < 32) b1s[threadIdx.x] = b1[threadIdx.x];
    __syncthreads();

    int row = (blockIdx.x * blockDim.x + threadIdx.x) >> 5;
    int lane = threadIdx.x & 31;
    if (row >= BN) return;
    int b    = row / N_NODES;
    int node = row - b * N_NODES;

    float xv = x[row * 32 + lane];
    float pa = 0.f;
    float pb = b1s[lane];
#pragma unroll
    for (int k = 0; k < 32; k++) {
        float xk = __shfl_sync(0xffffffffu, xv, k);
        pa = fmaf(xk, W1s[k * 32 + lane], pa);
        pb = fmaf(xk, W1s[(32 + k) * 32 + lane], pb);
    }
    reinterpret_cast<float*>(g_Pa4)[(node * 32 + lane) * 4 + b] = pa;
    reinterpret_cast<float*>(g_Pb4)[(node * 32 + lane) * 4 + b] = pb;
}

// ---------------------------------------------------------------------------
// Edge kernel: warp processes a 4-edge tile.
// Phase A (per edge g): lane=k. 2x LDG.128 gather (4 batches at once),
//   h1 = sig(pa+pb+ev*w1c) per batch, STS.128 into padded smem tile.
// Phase B: lanes = 4 edge-groups x 8 j-lanes; per k ONE LDS.128 delivers h1
//   (4 distinct 16B addrs, 528B group stride -> conflict-free) and ONE
//   LDS.128 delivers the W2 4-pack (broadcast across groups). 8 f32x2 FMA/k.
// Phase C: sigmoids + 8 RED.128 per tile into [node][j][b4] accumulator.
// ---------------------------------------------------------------------------
__global__ void __launch_bounds__(256) k_edge(const int* __restrict__ idx,
                                              const float* __restrict__ ea,
                                              const float* __restrict__ W1,
                                              const float* __restrict__ W2,
                                              const float* __restrict__ b2,
                                              int E) {
    const int lane = threadIdx.x & 31;
    const int wid  = threadIdx.x >> 5;
    const int jg   = lane & 7;        // j-lane within group
    const int grp  = lane >> 3;       // edge-group 0..3
    const unsigned full = 0xffffffffu;

    // h1 tile: per warp, 4 groups, stride 132 floats (528B) -> bank-offset 4/group
    __shared__ __align__(16) float h1s[8][4][132];
    // W2 packed: W2p[k][jg] = {W2[k][jg], W2[k][jg+8], W2[k][jg+16], W2[k][jg+24]}
    __shared__ __align__(16) float4 W2p[32][8];

    for (int t = threadIdx.x; t < 32 * 8; t += blockDim.x) {
        int k = t >> 3, j0 = t & 7;
        float4 w;
        w.x = W2[k * H2DIM + j0];
        w.y = W2[k * H2DIM + j0 + 8];
        w.z = W2[k * H2DIM + j0 + 16];
        w.w = (j0 + 24 < H2DIM) ? W2[k * H2DIM + j0 + 24] : 0.f;
        W2p[k][j0] = w;
    }
    __syncthreads();

    // Per-lane constants
    float w1cv = W1[64 * 32 + lane];              // used in phase A (lane=k)
    float b2v[4];
#pragma unroll
    for (int jj = 0; jj < 4; jj++) {
        int j = jg + 8 * jj;
        b2v[jj] = (j < H2DIM) ? b2[j] : 0.f;
    }

    // finalize stats locally
    float s  = g_sum, ss = g_sumsq;
    float mean   = s / (float)E;
    float invstd = rsqrtf((ss - s * s / (float)E) / (float)(E - 1));
    int   is32   = g_is32;

    int warp_global = (blockIdx.x * blockDim.x + threadIdx.x) >> 5;
    int base = warp_global * 32;
    if (base >= E) return;

    // Each lane loads one edge's metadata (coalesced)
    int e = base + lane;
    int src = 0, tgt = 0;
    float eav = 0.f;
    if (e < E) {
        if (is32) {
            src = idx[e];
            tgt = idx[E + e];
        } else {
            src = idx[2 * e];
            tgt = idx[2 * E + 2 * e];
        }
        eav = (ea[e] - mean) * invstd;
    }
    int cnt = min(32, E - base);

    uint32_t h1base = (uint32_t)__cvta_generic_to_shared(&h1s[wid][0][0]);
    uint32_t h1rd   = h1base + grp * 528;   // phase-B read base for this lane

#pragma unroll 1
    for (int i = 0; i < cnt; i += 4) {
        // ---- Phase A: fill h1 for edges i..i+3 ----
#pragma unroll
        for (int g = 0; g < 4; g++) {
            int   eg = i + g;
            int   sg = __shfl_sync(full, src, eg);
            int   tg = __shfl_sync(full, tgt, eg);
            float ev = __shfl_sync(full, eav, eg);
            if (eg < cnt) {
                float4 pa = g_Pa4[sg * 32 + lane];
                float4 pb = g_Pb4[tg * 32 + lane];
                float4 h;
                h.x = sigf(pa.x + pb.x + ev * w1cv);
                h.y = sigf(pa.y + pb.y + ev * w1cv);
                h.z = sigf(pa.z + pb.z + ev * w1cv);
                h.w = sigf(pa.w + pb.w + ev * w1cv);
                *reinterpret_cast<float4*>(&h1s[wid][g][lane * 4]) = h;
            }
        }
        __syncwarp(full);

        // ---- Phase B: layer-2 over k ----
        uint64_t s01[4], s23[4];
#pragma unroll
        for (int jj = 0; jj < 4; jj++) {
            asm("mov.b64 %0, {%1, %1};" : "=l"(s01[jj]) : "f"(b2v[jj]));
            s23[jj] = s01[jj];
        }
#pragma unroll 8
        for (int k = 0; k < 32; k++) {
            uint64_t h01, h23;
            asm("ld.shared.v2.u64 {%0, %1}, [%2];"
                : "=l"(h01), "=l"(h23) : "r"(h1rd + k * 16));
            float4 w = W2p[k][jg];
            uint64_t wp;
            asm("mov.b64 %0, {%1, %1};" : "=l"(wp) : "f"(w.x));
            asm("fma.rn.f32x2 %0, %1, %2, %0;" : "+l"(s01[0]) : "l"(h01), "l"(wp));
            asm("fma.rn.f32x2 %0, %1, %2, %0;" : "+l"(s23[0]) : "l"(h23), "l"(wp));
            asm("mov.b64 %0, {%1, %1};" : "=l"(wp) : "f"(w.y));
            asm("fma.rn.f32x2 %0, %1, %2, %0;" : "+l"(s01[1]) : "l"(h01), "l"(wp));
            asm("fma.rn.f32x2 %0, %1, %2, %0;" : "+l"(s23[1]) : "l"(h23), "l"(wp));
            asm("mov.b64 %0, {%1, %1};" : "=l"(wp) : "f"(w.z));
            asm("fma.rn.f32x2 %0, %1, %2, %0;" : "+l"(s01[2]) : "l"(h01), "l"(wp));
            asm("fma.rn.f32x2 %0, %1, %2, %0;" : "+l"(s23[2]) : "l"(h23), "l"(wp));
            asm("mov.b64 %0, {%1, %1};" : "=l"(wp) : "f"(w.w));
            asm("fma.rn.f32x2 %0, %1, %2, %0;" : "+l"(s01[3]) : "l"(h01), "l"(wp));
            asm("fma.rn.f32x2 %0, %1, %2, %0;" : "+l"(s23[3]) : "l"(h23), "l"(wp));
        }

        // ---- Phase C: sigmoid + scatter (lane handles its group's edge) ----
        bool actg = (i + grp) < cnt;
        int  tS = __shfl_sync(full, tgt, i + grp);
        int  sS = __shfl_sync(full, src, i + grp);
#pragma unroll
        for (int jj = 0; jj < 4; jj++) {
            int j = jg + 8 * jj;
            if (actg && j < H2DIM) {
                float v0, v1, v2, v3;
                asm("mov.b64 {%0, %1}, %2;" : "=f"(v0), "=f"(v1) : "l"(s01[jj]));
                asm("mov.b64 {%0, %1}, %2;" : "=f"(v2), "=f"(v3) : "l"(s23[jj]));
                float a = sigf(v0), b = sigf(v1), c = sigf(v2), d = sigf(v3);
                float4* pt = reinterpret_cast<float4*>(&g_acc[(tS * ACC_W + j) * 4]);
                float4* ps = reinterpret_cast<float4*>(&g_acc[(sS * ACC_W + j) * 4]);
                atomicAdd(pt, make_float4( a,  b,  c,  d));
                atomicAdd(ps, make_float4(-a, -b, -c, -d));
            }
        }
        __syncwarp(full);
    }
}

// ---------------------------------------------------------------------------
// Output: out[b][node][:] = sigmoid(acc[node][:30][b] @ W3 + b3).
// One warp per node; acc row loaded as float4 (4 batches), shfl broadcast.
// ---------------------------------------------------------------------------
__global__ void __launch_bounds__(256) k_out(const float* __restrict__ W3,
                                             const float* __restrict__ b3,
                                             float* __restrict__ out,
                                             int BN) {
    __shared__ float W3s[30 * 32];
    __shared__ float b3s[32];
    for (int i = threadIdx.x; i < 30 * 32; i += blockDim.x) W3s[i] = W3[i];
    if (threadIdx.x < 32) b3s[threadIdx.x] = b3[threadIdx.x];
    __syncthreads();

    int node = (blockIdx.x * blockDim.x + threadIdx.x) >> 5;
    int lane = threadIdx.x & 31;
    if (node >= N_NODES) return;
    const unsigned full = 0xffffffffu;

    // lane k holds acc[node][k][0..3]
    float4 a4 = *reinterpret_cast<const float4*>(&g_acc[(node * ACC_W + lane) * 4]);

    float o0 = b3s[lane], o1 = o0, o2 = o0, o3 = o0;
#pragma unroll
    for (int k = 0; k < 30; k++) {
        float w = W3s[k * 32 + lane];
        o0 = fmaf(__shfl_sync(full, a4.x, k), w, o0);
        o1 = fmaf(__shfl_sync(full, a4.y, k), w, o1);
        o2 = fmaf(__shfl_sync(full, a4.z, k), w, o2);
        o3 = fmaf(__shfl_sync(full, a4.w, k), w, o3);
    }
    int N32 = N_NODES * 32;
    out[0 * N32 + node * 32 + lane] = sigf(o0);
    out[1 * N32 + node * 32 + lane] = sigf(o1);
    out[2 * N32 + node * 32 + lane] = sigf(o2);
    out[3 * N32 + node * 32 + lane] = sigf(o3);
}

// ---------------------------------------------------------------------------
extern "C" void kernel_launch(void* const* d_in, const int* in_sizes, int n_in,
                              void* d_out, int out_size) {
    const float* x  = (const float*)d_in[0];
    const int*   ix = (const int*)  d_in[1];
    const float* ea = (const float*)d_in[2];
    const float* W1 = (const float*)d_in[3];
    const float* b1 = (const float*)d_in[4];
    const float* W2 = (const float*)d_in[5];
    const float* b2 = (const float*)d_in[6];
    const float* W3 = (const float*)d_in[7];
    const float* b3 = (const float*)d_in[8];

    int E  = in_sizes[2];            // edge_attr has E elements
    int BN = in_sizes[0] / FEAT;     // B * N rows

    int n_f4 = N_NODES * ACC_W;      // acc float4 count
    k_zero<<<(n_f4 + 255) / 256, 256>>>(n_f4, ix);
    k_stats<<<256, 256>>>(ea, E);
    k_proj<<<(BN + 7) / 8, 256>>>(x, W1, b1, BN);

    int warps = (E + 31) / 32;
    int blocks = (warps + 7) / 8;    // 8 warps (256 threads) per block
    k_edge<<<blocks, 256>>>(ix, ea, W1, W2, b2, E);

    k_out<<<(N_NODES + 7) / 8, 256>>>(W3, b3, (float*)d_out, BN);
}

// round 6
// speedup vs baseline: 10.9704x; 1.0839x over previous
#include <cuda_runtime.h>
#include <cuda_bf16.h>
#include <cstdint>

// Problem constants (fixed shapes for this dataset)
#define N_NODES 50000
#define N_BATCH 4
#define FEAT    32      // input feature dim, hidden1 dim, output dim
#define H2DIM   30      // hidden2 dim
#define ACC_W   32      // padded accumulator j-width (30 -> 32)

#define BN_MAX (N_BATCH * N_NODES)

// Device scratch.
//   g_PaH/g_PbH : [node][k][b] bf16 (4 batches -> 8B per (node,k))
//   g_acc       : [node][j][b] f32 (j padded to 32)
__device__ unsigned short g_PaH[N_NODES * FEAT * N_BATCH];
__device__ unsigned short g_PbH[N_NODES * FEAT * N_BATCH];
__device__ float  g_acc[N_NODES * ACC_W * N_BATCH];
__device__ float  g_sum, g_sumsq;
__device__ int    g_is32;               // 1 if edge_index is int32, 0 if int64

// sigmoid via single MUFU.TANH: sig(x) = 0.5*tanh(x/2) + 0.5
__device__ __forceinline__ float sigf(float x) {
    float t;
    asm("tanh.approx.f32 %0, %1;" : "=f"(t) : "f"(x * 0.5f));
    return fmaf(t, 0.5f, 0.5f);
}

// exact bf16 -> f32 (bits<<16)
__device__ __forceinline__ float bf_lo(uint32_t u) { return __uint_as_float(u << 16); }
__device__ __forceinline__ float bf_hi(uint32_t u) { return __uint_as_float(u & 0xffff0000u); }

// ---------------------------------------------------------------------------
// Fused init: zero accumulator + edge_attr stats + dtype detect
// ---------------------------------------------------------------------------
__global__ void k_init(int n_f4, const int* __restrict__ idx,
                       const float* __restrict__ ea, int E) {
    int i = blockIdx.x * blockDim.x + threadIdx.x;
    float4* p = reinterpret_cast<float4*>(g_acc);
    if (i < n_f4) p[i] = make_float4(0.f, 0.f, 0.f, 0.f);
    if (i == 0) { g_sum = 0.f; g_sumsq = 0.f; g_is32 = 0; }
    if (i < 2048) {
        if (idx[2 * i + 1] != 0) g_is32 = 1;   // benign race: only writes 1
    }

    // stats (grid-stride; grid is larger than E so usually 0-1 iters)
    float s = 0.f, ss = 0.f;
    for (int j = i; j < E; j += gridDim.x * blockDim.x) {
        float v = ea[j];
        s += v; ss += v * v;
    }
#pragma unroll
    for (int o = 16; o > 0; o >>= 1) {
        s  += __shfl_down_sync(0xffffffffu, s, o);
        ss += __shfl_down_sync(0xffffffffu, ss, o);
    }
    __shared__ float shs[8], shss[8];
    int w = threadIdx.x >> 5, l = threadIdx.x & 31;
    if (l == 0) { shs[w] = s; shss[w] = ss; }
    __syncthreads();
    if (threadIdx.x == 0) {
        float a = 0.f, b = 0.f;
        int nw = blockDim.x >> 5;
        for (int j = 0; j < nw; j++) { a += shs[j]; b += shss[j]; }
        if (a != 0.f || b != 0.f) {
            atomicAdd(&g_sum, a);
            atomicAdd(&g_sumsq, b);
        }
    }
}

// ---------------------------------------------------------------------------
// Per-(batch,node) projections: Pa = x@W1[0:32], Pb = x@W1[32:64] + b1.
// One warp per (b,node) row; stores bf16 into batch-interleaved layout.
// ---------------------------------------------------------------------------
__global__ void __launch_bounds__(256) k_proj(const float* __restrict__ x,
                                              const float* __restrict__ W1,
                                              const float* __restrict__ b1,
                                              int BN) {
    __shared__ float W1s[64 * 32];
    __shared__ float b1s[32];
    for (int i = threadIdx.x; i < 64 * 32; i += blockDim.x) W1s[i] = W1[i];
    if (threadIdx.x < 32) b1s[threadIdx.x] = b1[threadIdx.x];
    __syncthreads();

    int row = (blockIdx.x * blockDim.x + threadIdx.x) >> 5;
    int lane = threadIdx.x & 31;
    if (row >= BN) return;
    int b    = row / N_NODES;
    int node = row - b * N_NODES;

    float xv = x[row * 32 + lane];
    float pa = 0.f;
    float pb = b1s[lane];
#pragma unroll
    for (int k = 0; k < 32; k++) {
        float xk = __shfl_sync(0xffffffffu, xv, k);
        pa = fmaf(xk, W1s[k * 32 + lane], pa);
        pb = fmaf(xk, W1s[(32 + k) * 32 + lane], pb);
    }
    int o = (node * 32 + lane) * 4 + b;
    g_PaH[o] = __bfloat16_as_ushort(__float2bfloat16(pa));
    g_PbH[o] = __bfloat16_as_ushort(__float2bfloat16(pb));
}

// ---------------------------------------------------------------------------
// Edge kernel: warp processes a 4-edge tile.
// Phase A (per edge g): lane=k. 2x LDG.64 bf16 gather (4 batches), unpack,
//   h1 = sig(pa+pb+ev*w1c) per batch, STS.128 into padded smem tile.
// Phase B: lanes = 4 edge-groups x 8 j-lanes; per k ONE LDS.128 delivers h1
//   (4 distinct 16B addrs, 528B group stride -> conflict-free) and ONE
//   LDS.128 delivers the W2 4-pack (broadcast across groups). 8 f32x2 FMA/k.
// Phase C: sigmoids + 8 RED.128 per tile into [node][j][b4] accumulator.
// ---------------------------------------------------------------------------
__global__ void __launch_bounds__(256) k_edge(const int* __restrict__ idx,
                                              const float* __restrict__ ea,
                                              const float* __restrict__ W1,
                                              const float* __restrict__ W2,
                                              const float* __restrict__ b2,
                                              int E) {
    const int lane = threadIdx.x & 31;
    const int wid  = threadIdx.x >> 5;
    const int jg   = lane & 7;        // j-lane within group
    const int grp  = lane >> 3;       // edge-group 0..3
    const unsigned full = 0xffffffffu;

    // h1 tile: per warp, 4 groups, stride 132 floats (528B) -> bank-offset 4/group
    __shared__ __align__(16) float h1s[8][4][132];
    // W2 packed: W2p[k][jg] = {W2[k][jg], W2[k][jg+8], W2[k][jg+16], W2[k][jg+24]}
    __shared__ __align__(16) float4 W2p[32][8];

    for (int t = threadIdx.x; t < 32 * 8; t += blockDim.x) {
        int k = t >> 3, j0 = t & 7;
        float4 w;
        w.x = W2[k * H2DIM + j0];
        w.y = W2[k * H2DIM + j0 + 8];
        w.z = W2[k * H2DIM + j0 + 16];
        w.w = (j0 + 24 < H2DIM) ? W2[k * H2DIM + j0 + 24] : 0.f;
        W2p[k][j0] = w;
    }
    __syncthreads();

    // Per-lane constants
    float w1cv = W1[64 * 32 + lane];              // used in phase A (lane=k)
    float b2v[4];
#pragma unroll
    for (int jj = 0; jj < 4; jj++) {
        int j = jg + 8 * jj;
        b2v[jj] = (j < H2DIM) ? b2[j] : 0.f;
    }

    // finalize stats locally
    float s  = g_sum, ss = g_sumsq;
    float mean   = s / (float)E;
    float invstd = rsqrtf((ss - s * s / (float)E) / (float)(E - 1));
    int   is32   = g_is32;

    int warp_global = (blockIdx.x * blockDim.x + threadIdx.x) >> 5;
    int base = warp_global * 32;
    if (base >= E) return;

    // Each lane loads one edge's metadata (coalesced)
    int e = base + lane;
    int src = 0, tgt = 0;
    float eav = 0.f;
    if (e < E) {
        if (is32) {
            src = idx[e];
            tgt = idx[E + e];
        } else {
            src = idx[2 * e];
            tgt = idx[2 * E + 2 * e];
        }
        eav = (ea[e] - mean) * invstd;
    }
    int cnt = min(32, E - base);

    const uint2* PaV = reinterpret_cast<const uint2*>(g_PaH);
    const uint2* PbV = reinterpret_cast<const uint2*>(g_PbH);

    uint32_t h1base = (uint32_t)__cvta_generic_to_shared(&h1s[wid][0][0]);
    uint32_t h1rd   = h1base + grp * 528;   // phase-B read base for this lane

#pragma unroll 1
    for (int i = 0; i < cnt; i += 4) {
        // ---- Phase A: fill h1 for edges i..i+3 ----
#pragma unroll
        for (int g = 0; g < 4; g++) {
            int   eg = i + g;
            int   sg = __shfl_sync(full, src, eg);
            int   tg = __shfl_sync(full, tgt, eg);
            float ev = __shfl_sync(full, eav, eg);
            if (eg < cnt) {
                uint2 pa2 = PaV[sg * 32 + lane];
                uint2 pb2 = PbV[tg * 32 + lane];
                float c = ev * w1cv;
                float4 h;
                h.x = sigf(bf_lo(pa2.x) + bf_lo(pb2.x) + c);
                h.y = sigf(bf_hi(pa2.x) + bf_hi(pb2.x) + c);
                h.z = sigf(bf_lo(pa2.y) + bf_lo(pb2.y) + c);
                h.w = sigf(bf_hi(pa2.y) + bf_hi(pb2.y) + c);
                *reinterpret_cast<float4*>(&h1s[wid][g][lane * 4]) = h;
            }
        }
        __syncwarp(full);

        // ---- Phase B: layer-2 over k ----
        uint64_t s01[4], s23[4];
#pragma unroll
        for (int jj = 0; jj < 4; jj++) {
            asm("mov.b64 %0, {%1, %1};" : "=l"(s01[jj]) : "f"(b2v[jj]));
            s23[jj] = s01[jj];
        }
#pragma unroll 8
        for (int k = 0; k < 32; k++) {
            uint64_t h01, h23;
            asm("ld.shared.v2.u64 {%0, %1}, [%2];"
                : "=l"(h01), "=l"(h23) : "r"(h1rd + k * 16));
            float4 w = W2p[k][jg];
            uint64_t wp;
            asm("mov.b64 %0, {%1, %1};" : "=l"(wp) : "f"(w.x));
            asm("fma.rn.f32x2 %0, %1, %2, %0;" : "+l"(s01[0]) : "l"(h01), "l"(wp));
            asm("fma.rn.f32x2 %0, %1, %2, %0;" : "+l"(s23[0]) : "l"(h23), "l"(wp));
            asm("mov.b64 %0, {%1, %1};" : "=l"(wp) : "f"(w.y));
            asm("fma.rn.f32x2 %0, %1, %2, %0;" : "+l"(s01[1]) : "l"(h01), "l"(wp));
            asm("fma.rn.f32x2 %0, %1, %2, %0;" : "+l"(s23[1]) : "l"(h23), "l"(wp));
            asm("mov.b64 %0, {%1, %1};" : "=l"(wp) : "f"(w.z));
            asm("fma.rn.f32x2 %0, %1, %2, %0;" : "+l"(s01[2]) : "l"(h01), "l"(wp));
            asm("fma.rn.f32x2 %0, %1, %2, %0;" : "+l"(s23[2]) : "l"(h23), "l"(wp));
            asm("mov.b64 %0, {%1, %1};" : "=l"(wp) : "f"(w.w));
            asm("fma.rn.f32x2 %0, %1, %2, %0;" : "+l"(s01[3]) : "l"(h01), "l"(wp));
            asm("fma.rn.f32x2 %0, %1, %2, %0;" : "+l"(s23[3]) : "l"(h23), "l"(wp));
        }

        // ---- Phase C: sigmoid + scatter (lane handles its group's edge) ----
        bool actg = (i + grp) < cnt;
        int  tS = __shfl_sync(full, tgt, i + grp);
        int  sS = __shfl_sync(full, src, i + grp);
#pragma unroll
        for (int jj = 0; jj < 4; jj++) {
            int j = jg + 8 * jj;
            if (actg && j < H2DIM) {
                float v0, v1, v2, v3;
                asm("mov.b64 {%0, %1}, %2;" : "=f"(v0), "=f"(v1) : "l"(s01[jj]));
                asm("mov.b64 {%0, %1}, %2;" : "=f"(v2), "=f"(v3) : "l"(s23[jj]));
                float a = sigf(v0), b = sigf(v1), c = sigf(v2), d = sigf(v3);
                float4* pt = reinterpret_cast<float4*>(&g_acc[(tS * ACC_W + j) * 4]);
                float4* ps = reinterpret_cast<float4*>(&g_acc[(sS * ACC_W + j) * 4]);
                atomicAdd(pt, make_float4( a,  b,  c,  d));
                atomicAdd(ps, make_float4(-a, -b, -c, -d));
            }
        }
        __syncwarp(full);
    }
}

// ---------------------------------------------------------------------------
// Output: out[b][node][:] = sigmoid(acc[node][:30][b] @ W3 + b3).
// One warp per node; acc row loaded as float4 (4 batches), shfl broadcast.
// ---------------------------------------------------------------------------
__global__ void __launch_bounds__(256) k_out(const float* __restrict__ W3,
                                             const float* __restrict__ b3,
                                             float* __restrict__ out,
                                             int BN) {
    __shared__ float W3s[30 * 32];
    __shared__ float b3s[32];
    for (int i = threadIdx.x; i < 30 * 32; i += blockDim.x) W3s[i] = W3[i];
    if (threadIdx.x < 32) b3s[threadIdx.x] = b3[threadIdx.x];
    __syncthreads();

    int node = (blockIdx.x * blockDim.x + threadIdx.x) >> 5;
    int lane = threadIdx.x & 31;
    if (node >= N_NODES) return;
    const unsigned full = 0xffffffffu;

    // lane k holds acc[node][k][0..3]
    float4 a4 = *reinterpret_cast<const float4*>(&g_acc[(node * ACC_W + lane) * 4]);

    float o0 = b3s[lane], o1 = o0, o2 = o0, o3 = o0;
#pragma unroll
    for (int k = 0; k < 30; k++) {
        float w = W3s[k * 32 + lane];
        o0 = fmaf(__shfl_sync(full, a4.x, k), w, o0);
        o1 = fmaf(__shfl_sync(full, a4.y, k), w, o1);
        o2 = fmaf(__shfl_sync(full, a4.z, k), w, o2);
        o3 = fmaf(__shfl_sync(full, a4.w, k), w, o3);
    }
    int N32 = N_NODES * 32;
    out[0 * N32 + node * 32 + lane] = sigf(o0);
    out[1 * N32 + node * 32 + lane] = sigf(o1);
    out[2 * N32 + node * 32 + lane] = sigf(o2);
    out[3 * N32 + node * 32 + lane] = sigf(o3);
}

// ---------------------------------------------------------------------------
extern "C" void kernel_launch(void* const* d_in, const int* in_sizes, int n_in,
                              void* d_out, int out_size) {
    const float* x  = (const float*)d_in[0];
    const int*   ix = (const int*)  d_in[1];
    const float* ea = (const float*)d_in[2];
    const float* W1 = (const float*)d_in[3];
    const float* b1 = (const float*)d_in[4];
    const float* W2 = (const float*)d_in[5];
    const float* b2 = (const float*)d_in[6];
    const float* W3 = (const float*)d_in[7];
    const float* b3 = (const float*)d_in[8];

    int E  = in_sizes[2];            // edge_attr has E elements
    int BN = in_sizes[0] / FEAT;     // B * N rows

    int n_f4 = N_NODES * ACC_W;      // acc float4 count
    k_init<<<(n_f4 + 255) / 256, 256>>>(n_f4, ix, ea, E);
    k_proj<<<(BN + 7) / 8, 256>>>(x, W1, b1, BN);

    int warps = (E + 31) / 32;
    int blocks = (warps + 7) / 8;    // 8 warps (256 threads) per block
    k_edge<<<blocks, 256>>>(ix, ea, W1, W2, b2, E);

    k_out<<<(N_NODES + 7) / 8, 256>>>(W3, b3, (float*)d_out, BN);
}

// round 7
// speedup vs baseline: 11.1700x; 1.0182x over previous
#include <cuda_runtime.h>
#include <cuda_bf16.h>
#include <cstdint>

// Problem constants (fixed shapes for this dataset)
#define N_NODES 50000
#define N_BATCH 4
#define FEAT    32      // input feature dim, hidden1 dim, output dim
#define H2DIM   30      // hidden2 dim
#define ACC_W   32      // padded accumulator j-width (30 -> 32)

#define BN_MAX (N_BATCH * N_NODES)
#define GSTRIDE 144     // tile group stride in floats (bank-padded)

// Device scratch.
//   g_PaH/g_PbH : [node][k][b] bf16 (4 batches -> 8B per (node,k))
//   g_acc       : [node][j][b] f32 (j padded to 32)
__device__ unsigned short g_PaH[N_NODES * FEAT * N_BATCH];
__device__ unsigned short g_PbH[N_NODES * FEAT * N_BATCH];
__device__ float  g_acc[N_NODES * ACC_W * N_BATCH];
__device__ float  g_sum, g_sumsq;
__device__ int    g_is32;               // 1 if edge_index is int32, 0 if int64

// sigmoid via single MUFU.TANH: sig(x) = 0.5*tanh(x/2) + 0.5
__device__ __forceinline__ float sigf(float x) {
    float t;
    asm("tanh.approx.f32 %0, %1;" : "=f"(t) : "f"(x * 0.5f));
    return fmaf(t, 0.5f, 0.5f);
}

// exact bf16 -> f32 (bits<<16)
__device__ __forceinline__ float bf_lo(uint32_t u) { return __uint_as_float(u << 16); }
__device__ __forceinline__ float bf_hi(uint32_t u) { return __uint_as_float(u & 0xffff0000u); }

__device__ __forceinline__ uint32_t to_tf32(float v) {
    uint32_t r;
    asm("cvt.rna.tf32.f32 %0, %1;" : "=r"(r) : "f"(v));
    return r;
}

// ---------------------------------------------------------------------------
// Fused init: zero accumulator + edge_attr stats + dtype detect
// ---------------------------------------------------------------------------
__global__ void k_init(int n_f4, const int* __restrict__ idx,
                       const float* __restrict__ ea, int E) {
    int i = blockIdx.x * blockDim.x + threadIdx.x;
    float4* p = reinterpret_cast<float4*>(g_acc);
    if (i < n_f4) p[i] = make_float4(0.f, 0.f, 0.f, 0.f);
    if (i == 0) { g_sum = 0.f; g_sumsq = 0.f; g_is32 = 0; }
    if (i < 2048) {
        if (idx[2 * i + 1] != 0) g_is32 = 1;   // benign race: only writes 1
    }

    float s = 0.f, ss = 0.f;
    for (int j = i; j < E; j += gridDim.x * blockDim.x) {
        float v = ea[j];
        s += v; ss += v * v;
    }
#pragma unroll
    for (int o = 16; o > 0; o >>= 1) {
        s  += __shfl_down_sync(0xffffffffu, s, o);
        ss += __shfl_down_sync(0xffffffffu, ss, o);
    }
    __shared__ float shs[8], shss[8];
    int w = threadIdx.x >> 5, l = threadIdx.x & 31;
    if (l == 0) { shs[w] = s; shss[w] = ss; }
    __syncthreads();
    if (threadIdx.x == 0) {
        float a = 0.f, b = 0.f;
        int nw = blockDim.x >> 5;
        for (int j = 0; j < nw; j++) { a += shs[j]; b += shss[j]; }
        if (a != 0.f || b != 0.f) {
            atomicAdd(&g_sum, a);
            atomicAdd(&g_sumsq, b);
        }
    }
}

// ---------------------------------------------------------------------------
// Per-(batch,node) projections: Pa = x@W1[0:32], Pb = x@W1[32:64] + b1.
// One warp per (b,node) row; stores bf16 into batch-interleaved layout.
// ---------------------------------------------------------------------------
__global__ void __launch_bounds__(256) k_proj(const float* __restrict__ x,
                                              const float* __restrict__ W1,
                                              const float* __restrict__ b1,
                                              int BN) {
    __shared__ float W1s[64 * 32];
    __shared__ float b1s[32];
    for (int i = threadIdx.x; i < 64 * 32; i += blockDim.x) W1s[i] = W1[i];
    if (threadIdx.x < 32) b1s[threadIdx.x] = b1[threadIdx.x];
    __syncthreads();

    int row = (blockIdx.x * blockDim.x + threadIdx.x) >> 5;
    int lane = threadIdx.x & 31;
    if (row >= BN) return;
    int b    = row / N_NODES;
    int node = row - b * N_NODES;

    float xv = x[row * 32 + lane];
    float pa = 0.f;
    float pb = b1s[lane];
#pragma unroll
    for (int k = 0; k < 32; k++) {
        float xk = __shfl_sync(0xffffffffu, xv, k);
        pa = fmaf(xk, W1s[k * 32 + lane], pa);
        pb = fmaf(xk, W1s[(32 + k) * 32 + lane], pb);
    }
    int o = (node * 32 + lane) * 4 + b;
    g_PaH[o] = __bfloat16_as_ushort(__float2bfloat16(pa));
    g_PbH[o] = __bfloat16_as_ushort(__float2bfloat16(pb));
}

// ---------------------------------------------------------------------------
// Edge kernel: warp processes a 4-edge tile.
// Phase A (per edge g): lane=k. 2x LDG.64 bf16 gather, h1 = sig(...), STS.128
//   into buf[g][k][b] (g-stride GSTRIDE floats, bank-padded).
// Phase B: single m16n8k8 GEMM group: C[16x32] = h1[16x32] @ W2[32x32].
//   Rows r = gid-mapped (edge = r>>2, batch = r&3). W2 (tf32) lives in 32 regs
//   loaded once. 4 k-steps x (4 LDS.32 A-frag + 4 MMA). C init = bias.
//   Then sigmoid + 16 STS.32 write h2 back into the SAME buf as [g][j][b].
// Phase C: float4 re-read + RED.128 scatter into [node][j][b4] accumulator.
// ---------------------------------------------------------------------------
__global__ void __launch_bounds__(256) k_edge(const int* __restrict__ idx,
                                              const float* __restrict__ ea,
                                              const float* __restrict__ W1,
                                              const float* __restrict__ W2,
                                              const float* __restrict__ b2,
                                              int E) {
    const int lane = threadIdx.x & 31;
    const int wid  = threadIdx.x >> 5;
    const int jg   = lane & 7;        // phase-C j-lane within group
    const int grp  = lane >> 3;       // phase-C edge-group 0..3
    const int gid  = lane >> 2;       // mma group id 0..7
    const int tid  = lane & 3;        // mma thread-in-group
    const unsigned full = 0xffffffffu;

    // shared tile: h1 in phases A/B-read, h2 in B-write/C. [warp][g][GSTRIDE]
    __shared__ __align__(16) float buf[8][4 * GSTRIDE];

    // ---- W2 tf32 fragments (B operand), loaded once: b0/b1 per (s,t) ----
    // b0 = W2[8s+tid][8t+gid], b1 = W2[8s+tid+4][8t+gid]  (0 if j >= 30)
    uint32_t Bf[4][4][2];
    {
        int j = 8 * 0 + gid;   // recomputed in loop; placate compiler
        (void)j;
    }
#pragma unroll
    for (int s = 0; s < 4; s++) {
#pragma unroll
        for (int t = 0; t < 4; t++) {
            int j = 8 * t + gid;
            int k0 = 8 * s + tid;
            float w0 = (j < H2DIM) ? W2[k0 * H2DIM + j] : 0.f;
            float w1 = (j < H2DIM) ? W2[(k0 + 4) * H2DIM + j] : 0.f;
            Bf[s][t][0] = to_tf32(w0);
            Bf[s][t][1] = to_tf32(w1);
        }
    }

    // bias values for C init: j = 8t+2tid and +1
    float biasv[4][2];
#pragma unroll
    for (int t = 0; t < 4; t++) {
        int j = 8 * t + 2 * tid;
        biasv[t][0] = (j     < H2DIM) ? b2[j]     : 0.f;
        biasv[t][1] = (j + 1 < H2DIM) ? b2[j + 1] : 0.f;
    }

    // Per-lane constants for phase A (lane = k)
    float w1cv = W1[64 * 32 + lane];

    // finalize stats locally
    float s0  = g_sum, ss0 = g_sumsq;
    float mean   = s0 / (float)E;
    float invstd = rsqrtf((ss0 - s0 * s0 / (float)E) / (float)(E - 1));
    int   is32   = g_is32;

    int warp_global = (blockIdx.x * blockDim.x + threadIdx.x) >> 5;
    int base = warp_global * 32;
    if (base >= E) return;

    int e = base + lane;
    int src = 0, tgt = 0;
    float eav = 0.f;
    if (e < E) {
        if (is32) {
            src = idx[e];
            tgt = idx[E + e];
        } else {
            src = idx[2 * e];
            tgt = idx[2 * E + 2 * e];
        }
        eav = (ea[e] - mean) * invstd;
    }
    int cnt = min(32, E - base);

    const uint2* PaV = reinterpret_cast<const uint2*>(g_PaH);
    const uint2* PbV = reinterpret_cast<const uint2*>(g_PbH);

    uint32_t bufB = (uint32_t)__cvta_generic_to_shared(&buf[wid][0]);
    // A-fragment base: g = gid>>2 (rows gid / gid+8 -> edges gid>>2 / +2)
    uint32_t aB  = bufB + (gid >> 2) * (GSTRIDE * 4) + tid * 16 + (gid & 3) * 4;
    // h2 writeback base: row gid -> edge gid>>2, batch gid&3
    uint32_t cB  = bufB + (gid >> 2) * (GSTRIDE * 4) + (gid & 3) * 4;
    // phase-C read base
    uint32_t rB  = bufB + grp * (GSTRIDE * 4);

#pragma unroll 1
    for (int i = 0; i < cnt; i += 4) {
        // ---- Phase A: fill h1 for edges i..i+3 ----
#pragma unroll
        for (int g = 0; g < 4; g++) {
            int   eg = i + g;
            int   sg = __shfl_sync(full, src, eg);
            int   tg = __shfl_sync(full, tgt, eg);
            float ev = __shfl_sync(full, eav, eg);
            if (eg < cnt) {
                uint2 pa2 = PaV[sg * 32 + lane];
                uint2 pb2 = PbV[tg * 32 + lane];
                float c = ev * w1cv;
                float4 h;
                h.x = sigf(bf_lo(pa2.x) + bf_lo(pb2.x) + c);
                h.y = sigf(bf_hi(pa2.x) + bf_hi(pb2.x) + c);
                h.z = sigf(bf_lo(pa2.y) + bf_lo(pb2.y) + c);
                h.w = sigf(bf_hi(pa2.y) + bf_hi(pb2.y) + c);
                *reinterpret_cast<float4*>(&buf[wid][g * GSTRIDE + lane * 4]) = h;
            }
        }
        __syncwarp(full);

        // ---- Phase B: tf32 MMA, C[16x32] ----
        float c0[4], c1[4], c2[4], c3[4];
#pragma unroll
        for (int t = 0; t < 4; t++) {
            c0[t] = biasv[t][0]; c1[t] = biasv[t][1];
            c2[t] = biasv[t][0]; c3[t] = biasv[t][1];
        }
#pragma unroll
        for (int s = 0; s < 4; s++) {
            float fa0, fa1, fa2, fa3;
            uint32_t ad = aB + s * 128;           // k = 8s+tid -> 16B per k
            asm("ld.shared.b32 %0, [%1];"       : "=f"(fa0) : "r"(ad));
            asm("ld.shared.b32 %0, [%1+1152];"  : "=f"(fa1) : "r"(ad));  // g+2
            asm("ld.shared.b32 %0, [%1+64];"    : "=f"(fa2) : "r"(ad));  // k+4
            asm("ld.shared.b32 %0, [%1+1216];"  : "=f"(fa3) : "r"(ad));
            uint32_t a0 = to_tf32(fa0), a1 = to_tf32(fa1);
            uint32_t a2 = to_tf32(fa2), a3 = to_tf32(fa3);
#pragma unroll
            for (int t = 0; t < 4; t++) {
                asm("mma.sync.aligned.m16n8k8.row.col.f32.tf32.tf32.f32 "
                    "{%0,%1,%2,%3}, {%4,%5,%6,%7}, {%8,%9}, {%0,%1,%2,%3};"
                    : "+f"(c0[t]), "+f"(c1[t]), "+f"(c2[t]), "+f"(c3[t])
                    : "r"(a0), "r"(a1), "r"(a2), "r"(a3),
                      "r"(Bf[s][t][0]), "r"(Bf[s][t][1]));
            }
        }
        __syncwarp(full);   // all A-frag reads done before h2 overwrites buf

        // ---- sigmoid + writeback h2 into buf as [g][j][b] ----
#pragma unroll
        for (int t = 0; t < 4; t++) {
            int j = 8 * t + 2 * tid;
            float v0 = sigf(c0[t]), v1 = sigf(c1[t]);
            float v2 = sigf(c2[t]), v3 = sigf(c3[t]);
            uint32_t a = cB + j * 16;
            asm volatile("st.shared.b32 [%0], %1;"       :: "r"(a), "f"(v0));
            asm volatile("st.shared.b32 [%0+16], %1;"    :: "r"(a), "f"(v1));
            asm volatile("st.shared.b32 [%0+1152], %1;"  :: "r"(a), "f"(v2)); // edge+2
            asm volatile("st.shared.b32 [%0+1168], %1;"  :: "r"(a), "f"(v3));
        }
        __syncwarp(full);

        // ---- Phase C: float4 re-read + scatter ----
        bool actg = (i + grp) < cnt;
        int  tS = __shfl_sync(full, tgt, i + grp);
        int  sS = __shfl_sync(full, src, i + grp);
#pragma unroll
        for (int jj = 0; jj < 4; jj++) {
            int j = jg + 8 * jj;
            if (actg && j < H2DIM) {
                float4 h2;
                asm("ld.shared.v4.f32 {%0,%1,%2,%3}, [%4];"
                    : "=f"(h2.x), "=f"(h2.y), "=f"(h2.z), "=f"(h2.w)
                    : "r"(rB + j * 16));
                float4* pt = reinterpret_cast<float4*>(&g_acc[(tS * ACC_W + j) * 4]);
                float4* ps = reinterpret_cast<float4*>(&g_acc[(sS * ACC_W + j) * 4]);
                atomicAdd(pt, make_float4( h2.x,  h2.y,  h2.z,  h2.w));
                atomicAdd(ps, make_float4(-h2.x, -h2.y, -h2.z, -h2.w));
            }
        }
        __syncwarp(full);
    }
}

// ---------------------------------------------------------------------------
// Output: out[b][node][:] = sigmoid(acc[node][:30][b] @ W3 + b3).
// One warp per node; acc row loaded as float4 (4 batches), shfl broadcast.
// ---------------------------------------------------------------------------
__global__ void __launch_bounds__(256) k_out(const float* __restrict__ W3,
                                             const float* __restrict__ b3,
                                             float* __restrict__ out,
                                             int BN) {
    __shared__ float W3s[30 * 32];
    __shared__ float b3s[32];
    for (int i = threadIdx.x; i < 30 * 32; i += blockDim.x) W3s[i] = W3[i];
    if (threadIdx.x < 32) b3s[threadIdx.x] = b3[threadIdx.x];
    __syncthreads();

    int node = (blockIdx.x * blockDim.x + threadIdx.x) >> 5;
    int lane = threadIdx.x & 31;
    if (node >= N_NODES) return;
    const unsigned full = 0xffffffffu;

    float4 a4 = *reinterpret_cast<const float4*>(&g_acc[(node * ACC_W + lane) * 4]);

    float o0 = b3s[lane], o1 = o0, o2 = o0, o3 = o0;
#pragma unroll
    for (int k = 0; k < 30; k++) {
        float w = W3s[k * 32 + lane];
        o0 = fmaf(__shfl_sync(full, a4.x, k), w, o0);
        o1 = fmaf(__shfl_sync(full, a4.y, k), w, o1);
        o2 = fmaf(__shfl_sync(full, a4.z, k), w, o2);
        o3 = fmaf(__shfl_sync(full, a4.w, k), w, o3);
    }
    int N32 = N_NODES * 32;
    out[0 * N32 + node * 32 + lane] = sigf(o0);
    out[1 * N32 + node * 32 + lane] = sigf(o1);
    out[2 * N32 + node * 32 + lane] = sigf(o2);
    out[3 * N32 + node * 32 + lane] = sigf(o3);
}

// ---------------------------------------------------------------------------
extern "C" void kernel_launch(void* const* d_in, const int* in_sizes, int n_in,
                              void* d_out, int out_size) {
    const float* x  = (const float*)d_in[0];
    const int*   ix = (const int*)  d_in[1];
    const float* ea = (const float*)d_in[2];
    const float* W1 = (const float*)d_in[3];
    const float* b1 = (const float*)d_in[4];
    const float* W2 = (const float*)d_in[5];
    const float* b2 = (const float*)d_in[6];
    const float* W3 = (const float*)d_in[7];
    const float* b3 = (const float*)d_in[8];

    int E  = in_sizes[2];            // edge_attr has E elements
    int BN = in_sizes[0] / FEAT;     // B * N rows

    int n_f4 = N_NODES * ACC_W;      // acc float4 count
    k_init<<<(n_f4 + 255) / 256, 256>>>(n_f4, ix, ea, E);
    k_proj<<<(BN + 7) / 8, 256>>>(x, W1, b1, BN);

    int warps = (E + 31) / 32;
    int blocks = (warps + 7) / 8;    // 8 warps (256 threads) per block
    k_edge<<<blocks, 256>>>(ix, ea, W1, W2, b2, E);

    k_out<<<(N_NODES + 7) / 8, 256>>>(W3, b3, (float*)d_out, BN);
}